// round 10
// baseline (speedup 1.0000x reference)
#include <cuda_runtime.h>
#include <cstdint>
#include <math.h>

#define NUM_CLASSES 80
#define HW 65536
#define TOPK 100
#define CAND_CAP (NUM_CLASSES * HW)
#define FINAL_CAP 2048
#define STAGE_CAP 1024
#define PEAK_BLOCKS (NUM_CLASSES * 8)
#define FILTER_BLOCKS 96
#define SVSTRIDE 264               // smem row stride (floats), 16B aligned

// ---------------- device scratch (left zeroed at end of every call) ----------------
__device__ unsigned long long g_cands[CAND_CAP];
__device__ unsigned int       g_hist[65536];
__device__ unsigned int       g_counter;
__device__ unsigned int       g_nfinal;
__device__ unsigned int       g_threshold;
__device__ unsigned int       g_done1;
__device__ unsigned int       g_done2;
__device__ unsigned long long g_final[FINAL_CAP];

__device__ __forceinline__ float sigm(float x) {
    return 1.0f / (1.0f + __expf(-x));
}
__device__ __forceinline__ float sigm_acc(float x) {
    return 1.0f / (1.0f + expf(-x));
}

// ================= kernel 1: peak detect + (last block) threshold =================
// Block = 256 threads = one 32-row x 256-col strip of one class (batch 0).
// Vertical 5-max in registers (thread = column), horizontal 5-max vectorized from smem.
__global__ __launch_bounds__(256, 5) void peakKernel(const float* __restrict__ cls) {
    extern __shared__ float smem[];
    float* sV = smem;                                   // 32 x SVSTRIDE, col idx = c+4
    unsigned long long* sKeys =
        (unsigned long long*)(smem + 32 * SVSTRIDE);    // STAGE_CAP
    __shared__ unsigned sCnt, sBase, sIsLast, sJc, sAbove, sTotal;

    const int c    = blockIdx.x >> 3;
    const int row0 = (blockIdx.x & 7) << 5;
    const float* base = cls + (size_t)c * HW;
    const int t = threadIdx.x;
    const int lane = t & 31;
    if (t == 0) sCnt = 0u;

    // column pads (-1e30): idx 0..3 and 260..263 for all 32 rows
    {
        int r = t >> 3, pc = t & 7;
        int idx = (pc < 4) ? pc : (256 + pc);
        sV[r * SVSTRIDE + idx] = -1e30f;
    }

    // ---- vertical pass: simple fully-unrolled 5-tap shift register, col = t ----
    {
        const float* colp = base + t;
        #define LOADROW(gr) (((unsigned)(gr) < 256u) ? __ldg(colp + ((gr) << 8)) : -1e30f)
        float w0 = LOADROW(row0 - 2);
        float w1 = LOADROW(row0 - 1);
        float w2 = LOADROW(row0 + 0);
        float w3 = LOADROW(row0 + 1);
        #pragma unroll
        for (int k = 0; k < 32; k++) {
            float w4 = LOADROW(row0 + k + 2);
            sV[k * SVSTRIDE + 4 + t] =
                fmaxf(fmaxf(fmaxf(w0, w1), fmaxf(w2, w3)), w4);
            w0 = w1; w1 = w2; w2 = w3; w3 = w4;
        }
        #undef LOADROW
    }
    __syncthreads();

    const unsigned lt = (1u << lane) - 1u;

    // ---- horizontal pass + emit: 8 passes, 4 outputs/thread/pass ----
    #pragma unroll 2
    for (int p = 0; p < 8; p++) {
        const int r  = (t >> 6) + (p << 2);        // 0..31
        const int c0 = (t & 63) << 2;              // 0..252
        const float* row = &sV[r * SVSTRIDE];
        float4 a  = *(const float4*)&row[c0];      // cols c0-4..c0-1
        float4 b  = *(const float4*)&row[c0 + 4];  // cols c0..c0+3
        float4 cv = *(const float4*)&row[c0 + 8];  // cols c0+4..c0+7

        float mb01 = fmaxf(b.x, b.y);
        float mb23 = fmaxf(b.z, b.w);
        float m0 = fmaxf(fmaxf(a.z, a.w), fmaxf(mb01, b.z));
        float m1 = fmaxf(a.w, fmaxf(mb01, mb23));
        float m2 = fmaxf(fmaxf(mb01, mb23), cv.x);
        float m3 = fmaxf(fmaxf(b.y, b.z), fmaxf(b.w, fmaxf(cv.x, cv.y)));

        // center logits (coalesced float4, L2-hot)
        float4 ctr = __ldg((const float4*)(base + ((row0 + r) << 8) + c0));

        float ms[4] = {m0, m1, m2, m3};
        float xs[4] = {ctr.x, ctr.y, ctr.z, ctr.w};
        #pragma unroll
        for (int j = 0; j < 4; j++) {
            float m = ms[j], x = xs[j];
            bool keep = (m == x);
            float score = 0.0f;
            if (keep) {
                score = sigm(x);
            } else if (m - x < 1e-3f) {
                float sm = sigm_acc(m), sx = sigm_acc(x);
                if (__float_as_uint(sm) == __float_as_uint(sx)) { keep = true; score = sx; }
            }
            unsigned mball = __ballot_sync(0xFFFFFFFFu, keep);
            if (mball) {
                unsigned wbase = 0;
                if (lane == 0) wbase = atomicAdd(&sCnt, (unsigned)__popc(mball));
                wbase = __shfl_sync(0xFFFFFFFFu, wbase, 0);
                if (keep) {
                    unsigned hw  = (unsigned)(((row0 + r) << 8) | (c0 + j));
                    unsigned idx = ((unsigned)c << 16) | hw;
                    unsigned sb  = __float_as_uint(score);
                    unsigned long long key =
                        ((unsigned long long)sb << 32) | (0xFFFFFFFFu - idx);
                    unsigned pos = wbase + (unsigned)__popc(mball & lt);
                    if (pos < STAGE_CAP) {
                        sKeys[pos] = key;
                    } else {                       // pathological overflow spill
                        unsigned g = atomicAdd(&g_counter, 1u);
                        g_cands[g] = key;
                    }
                    atomicAdd(&g_hist[sb >> 16], 1u);
                }
            }
        }
    }
    __syncthreads();

    unsigned M = sCnt; if (M > STAGE_CAP) M = STAGE_CAP;
    if (t == 0) sBase = atomicAdd(&g_counter, M);
    __syncthreads();
    for (unsigned i = t; i < M; i += 256) g_cands[sBase + i] = sKeys[i];

    // ---- decoupled last block: threshold from histogram, zero hist, reset ticket ----
    __threadfence();
    if (t == 0) sIsLast = (atomicAdd(&g_done1, 1u) == PEAK_BLOCKS - 1u) ? 1u : 0u;
    __syncthreads();
    if (!sIsLast) return;

    unsigned* sa = (unsigned*)smem;      // 256
    unsigned* sb = sa + 256;             // 256
    unsigned* sc = sb + 256;             // 256

    // 256 chunk sums (256 bins each), warp-coalesced
    const int w = t >> 5;
    for (int j = w; j < 256; j += 8) {
        unsigned s = 0;
        #pragma unroll
        for (int k = 0; k < 8; k++) s += g_hist[j * 256 + k * 32 + lane];
        #pragma unroll
        for (int o2 = 16; o2; o2 >>= 1) s += __shfl_down_sync(0xFFFFFFFFu, s, o2);
        if (lane == 0) sa[j] = s;
    }
    __syncthreads();

    // suffix scan over 256 chunks
    unsigned* src = sa; unsigned* dst = sb;
    for (int off = 1; off < 256; off <<= 1) {
        unsigned v = src[t];
        if (t + off < 256) v += src[t + off];
        __syncthreads();
        dst[t] = v;
        __syncthreads();
        unsigned* tmp = src; src = dst; dst = tmp;
    }
    if (t == 0) { sTotal = src[0]; sJc = 0u; sAbove = 0u; }
    __syncthreads();
    {
        unsigned nx = (t < 255) ? src[t + 1] : 0u;
        if (src[t] >= TOPK && nx < TOPK) { sJc = (unsigned)t; sAbove = nx; }
    }
    __syncthreads();

    if (sTotal < TOPK) {
        if (t == 0) g_threshold = 0u;
    } else {
        const unsigned jc = sJc, above = sAbove;
        sc[t] = g_hist[jc * 256 + t];
        __syncthreads();
        unsigned* fsrc = sc; unsigned* fdst = (src == sa) ? sb : sa;
        for (int off = 1; off < 256; off <<= 1) {
            unsigned v = fsrc[t];
            if (t + off < 256) v += fsrc[t + off];
            __syncthreads();
            fdst[t] = v;
            __syncthreads();
            unsigned* tmp = fsrc; fsrc = fdst; fdst = tmp;
        }
        unsigned g1 = above + fsrc[t];
        unsigned g2 = above + ((t < 255) ? fsrc[t + 1] : 0u);
        if (g1 >= TOPK && g2 < TOPK) g_threshold = jc * 256 + (unsigned)t;
    }
    __syncthreads();

    for (int i = t; i < 16384; i += 256)
        ((uint4*)g_hist)[i] = make_uint4(0u, 0u, 0u, 0u);
    if (t == 0) g_done1 = 0u;
}

// ================= kernel 2: filter + (last block) sort/emit =================
__global__ __launch_bounds__(512) void filterEmitKernel(const float* __restrict__ txty,
                                                        float* __restrict__ out,
                                                        int out_size) {
    __shared__ unsigned long long keys[FINAL_CAP];
    __shared__ unsigned sIsLast;
    const int t = threadIdx.x;
    const unsigned N = g_counter;
    const unsigned T = g_threshold;
    const unsigned stride = gridDim.x * blockDim.x;
    for (unsigned i = blockIdx.x * blockDim.x + t; i < N; i += stride) {
        unsigned long long k = g_cands[i];
        if ((unsigned)(k >> 48) >= T) {
            unsigned p = atomicAdd(&g_nfinal, 1u);
            if (p < FINAL_CAP) g_final[p] = k;
        }
    }
    __threadfence();
    if (t == 0) sIsLast = (atomicAdd(&g_done2, 1u) == FILTER_BLOCKS - 1u) ? 1u : 0u;
    __syncthreads();
    if (!sIsLast) return;

    unsigned M = atomicAdd(&g_nfinal, 0u);
    if (M > FINAL_CAP) M = FINAL_CAP;
    int P = 256; while (P < (int)M) P <<= 1;

    for (int i = t; i < P; i += 512)
        keys[i] = (i < (int)M) ? __ldcg(&g_final[i]) : 0ULL;
    __syncthreads();

    for (int k = 2; k <= P; k <<= 1) {
        for (int j = k >> 1; j > 0; j >>= 1) {
            for (int i = t; i < P; i += 512) {
                int ixj = i ^ j;
                if (ixj > i) {
                    unsigned long long A = keys[i], B = keys[ixj];
                    bool desc = ((i & k) == 0);
                    if (desc ? (A < B) : (A > B)) { keys[i] = B; keys[ixj] = A; }
                }
            }
            __syncthreads();
        }
    }

    if (t < TOPK) {
        unsigned long long key = keys[t];
        float score  = __uint_as_float((unsigned)(key >> 32));
        unsigned idx = 0xFFFFFFFFu - (unsigned)(key & 0xFFFFFFFFu);
        unsigned cls = idx >> 16;
        unsigned hw  = idx & 0xFFFFu;
        unsigned gy  = hw >> 8, gx = hw & 0xFFu;
        float tx = __ldg(&txty[hw]);
        float ty = __ldg(&txty[HW + hw]);
        float bx = (sigm(tx) + (float)gx) * (4.0f / 1024.0f);
        float by = (sigm(ty) + (float)gy) * (4.0f / 1024.0f);
        bx = fminf(fmaxf(bx, 0.0f), 1.0f);
        by = fminf(fmaxf(by, 0.0f), 1.0f);
        out[t * 4 + 0] = bx;
        out[t * 4 + 1] = by;
        out[t * 4 + 2] = 0.0f;
        out[t * 4 + 3] = 0.0f;
        out[400 + t] = score;
        out[500 + t] = (float)cls;
    }
    for (int i = 600 + t; i < out_size; i += 512) out[i] = 0.0f;
    __syncthreads();
    if (t == 0) { g_counter = 0u; g_nfinal = 0u; g_threshold = 0u; g_done2 = 0u; }
}

// ---------------- launch ----------------
extern "C" void kernel_launch(void* const* d_in, const int* in_sizes, int n_in,
                              void* d_out, int out_size) {
    const float* cls  = (const float*)d_in[0];
    const float* txty = (const float*)d_in[1];
    float* out = (float*)d_out;

    const int peakSmem = 32 * SVSTRIDE * 4 + STAGE_CAP * 8;  // 41,984 B (< 48KB default)
    peakKernel<<<PEAK_BLOCKS, 256, peakSmem>>>(cls);
    filterEmitKernel<<<FILTER_BLOCKS, 512>>>(txty, out, out_size);
}